// round 16
// baseline (speedup 1.0000x reference)
#include <cuda_runtime.h>
#include <cuda_fp16.h>
#include <cstdint>
#include <math.h>

#define SS    128
#define LFREQ 10

__device__ float g_dt;
__device__ __align__(16) unsigned char g_wbuf[20480];   // pre-swizzled fp16 weights

#define GW_W1 0
#define GW_W2 8192
#define GW_WO 16384

// ---------------- helpers ----------------
__device__ __forceinline__ uint32_t smem_to_u32(const void* p) {
    uint32_t a;
    asm("{ .reg .u64 t; cvta.to.shared.u64 t, %1; cvt.u32.u64 %0, t; }" : "=r"(a) : "l"(p));
    return a;
}

__device__ __forceinline__ void ldsm4(uint32_t* r, uint32_t addr) {
    asm volatile("ldmatrix.sync.aligned.m8n8.x4.shared.b16 {%0,%1,%2,%3}, [%4];"
        : "=r"(r[0]), "=r"(r[1]), "=r"(r[2]), "=r"(r[3]) : "r"(addr));
}

__device__ __forceinline__ void mma16816(float* d, const uint32_t* a, uint32_t b0, uint32_t b1) {
    asm volatile("mma.sync.aligned.m16n8k16.row.col.f32.f16.f16.f32 "
        "{%0,%1,%2,%3}, {%4,%5,%6,%7}, {%8,%9}, {%0,%1,%2,%3};"
        : "+f"(d[0]), "+f"(d[1]), "+f"(d[2]), "+f"(d[3])
        : "r"(a[0]), "r"(a[1]), "r"(a[2]), "r"(a[3]), "r"(b0), "r"(b1));
}

__device__ __forceinline__ uint32_t pack2h(float a, float b) {
    __half2 hh = __floats2half2_rn(a, b);
    return *reinterpret_cast<uint32_t*>(&hh);
}

// insert fp16 of v into half (idx&1) of hi[idx>>1]; idx must be compile-time
__device__ __forceinline__ void put_h(uint32_t* hi, int idx, float v) {
    __half h = __float2half_rn(v);
    uint32_t u = (uint32_t)(*reinterpret_cast<uint16_t*>(&h));
    if (idx & 1) hi[idx >> 1] = (hi[idx >> 1] & 0x0000FFFFu) | (u << 16);
    else         hi[idx >> 1] = (hi[idx >> 1] & 0xFFFF0000u) | u;
}

// swizzled tile byte offset: row-major, 128B rows, 16B granules XORed
__device__ __forceinline__ uint32_t sw_off(int row, int c4) {
    return (uint32_t)(row * 128 + ((c4 ^ (row & 7)) << 4));
}

// ---------------- SMEM layout (byte offsets) ----------------
#define SM_B1    0
#define SM_B2    256
#define SM_BO    512
#define SM_WRGB  640
#define SM_BRGB  832
#define SM_W     1024
#define SM_W1    (SM_W + GW_W1)
#define SM_W2    (SM_W + GW_W2)
#define SM_WO    (SM_W + GW_WO)
#define SM_A     21504   // 128 x 128B fp16 tile = 16384
#define SM_TOTAL (21504 + 16384)   // 37888

#define OSTRIDE 21       // OUT staging stride in floats (coprime with 32 banks)
#define TPB 128

// -------- prep: dt reduction + weight conversion (one CTA) --------
__global__ void prep_kernel(const float* __restrict__ tmin, const float* __restrict__ tmax,
                            const float* __restrict__ W1, const float* __restrict__ W2,
                            const float* __restrict__ Wo, int n) {
    __shared__ float red[256];
    int tid = threadIdx.x;
    float acc = 0.f;
    for (int i = tid; i < n; i += 256) acc += tmax[i] - tmin[i];
    red[tid] = acc;
    __syncthreads();
    for (int s = 128; s > 0; s >>= 1) {
        if (tid < s) red[tid] += red[tid + s];
        __syncthreads();
    }
    if (tid == 0) g_dt = (red[0] / (float)n) / (float)SS;

    for (int idx = tid; idx < 64 * 64; idx += 256) {
        int nn = idx >> 6, k = idx & 63;
        float w = (k < 63) ? W1[k * 64 + nn] : 0.f;
        __half h = __float2half_rn(w);
        uint32_t off = sw_off(nn, k >> 3) + (k & 7) * 2;
        *(uint16_t*)(g_wbuf + GW_W1 + off) = *reinterpret_cast<uint16_t*>(&h);
    }
    for (int idx = tid; idx < 64 * 64; idx += 256) {
        int nn = idx >> 6, k = idx & 63;
        float w = W2[k * 64 + nn];
        __half h = __float2half_rn(w);
        uint32_t off = sw_off(nn, k >> 3) + (k & 7) * 2;
        *(uint16_t*)(g_wbuf + GW_W2 + off) = *reinterpret_cast<uint16_t*>(&h);
    }
    for (int idx = tid; idx < 32 * 64; idx += 256) {
        int nn = idx >> 6, k = idx & 63;
        float w = (nn < 17) ? Wo[k * 17 + nn] : 0.f;
        __half h = __float2half_rn(w);
        uint32_t off = sw_off(nn, k >> 3) + (k & 7) * 2;
        *(uint16_t*)(g_wbuf + GW_WO + off) = *reinterpret_cast<uint16_t*>(&h);
    }
}

__global__ void __launch_bounds__(TPB, 6)
nerf_mma_kernel(const float* __restrict__ ox, const float* __restrict__ oy,
                const float* __restrict__ oz, const float* __restrict__ dxv,
                const float* __restrict__ dyv, const float* __restrict__ dzv,
                const float* __restrict__ tmin, const float* __restrict__ tmax,
                const float* __restrict__ b1, const float* __restrict__ b2,
                const float* __restrict__ bo,
                const float* __restrict__ Wrgb, const float* __restrict__ brgb,
                float* __restrict__ out, int n)
{
    extern __shared__ __align__(1024) char smem[];
    const uint32_t sb = smem_to_u32(smem);
    const int tid  = threadIdx.x;
    const int lid  = tid & 31;
    const int wid  = tid >> 5;            // 0..3
    const int wbase = wid * 32;           // 32 rows per warp (2 m-tiles)
    const uint32_t AH = SM_A;
    const int ray = blockIdx.x;

    // ---- stage weights (vector copy of preconverted fp16 tiles) ----
    {
        const uint4* src = (const uint4*)g_wbuf;
        uint4* dst = (uint4*)(smem + SM_W);
        for (int i = tid; i < 1280; i += TPB) dst[i] = src[i];
        float* s = (float*)smem;
        for (int i = tid; i < 64; i += TPB) s[(SM_B1 >> 2) + i] = b1[i];
        for (int i = tid; i < 64; i += TPB) s[(SM_B2 >> 2) + i] = b2[i];
        for (int i = tid; i < 17; i += TPB) s[(SM_BO >> 2) + i] = bo[i];
        for (int i = tid; i < 48; i += TPB) s[(SM_WRGB >> 2) + i] = Wrgb[i];
        for (int i = tid; i < 3;  i += TPB) s[(SM_BRGB >> 2) + i] = brgb[i];
    }

    // ---- positional encodings -> packed fp16 pairs, low register pressure ----
    {
        const float tmn = tmin[ray], tmx = tmax[ray];
        const float t  = fmaf((float)tid * (1.0f / (float)(SS - 1)), tmx - tmn, tmn);
        const float px = fmaf(dxv[ray], t, ox[ray]);
        const float py = fmaf(dyv[ray], t, oy[ray]);
        const float pz = fmaf(dzv[ray], t, oz[ray]);
        uint32_t hi[32];
        hi[0] = pack2h(px, py);
        hi[31] = 0;
        put_h(hi, 2, pz);
#pragma unroll
        for (int c = 0; c < 3; c++) {
            float sv, cv;
            __sincosf((c == 0) ? px : ((c == 1) ? py : pz), &sv, &cv);
#pragma unroll
            for (int f = 0; f < LFREQ; f++) {
                put_h(hi, 3 + 20 * c + f,      sv);
                put_h(hi, 3 + 20 * c + 10 + f, cv);
                float ns = 2.0f * sv * cv;
                float nc = fmaf(cv, cv, -(sv * sv));
                sv = ns; cv = nc;
            }
        }
#pragma unroll
        for (int q = 0; q < 8; q++) {
            uint32_t off = sw_off(tid, q);
            *(uint4*)(smem + AH + off) = make_uint4(hi[4*q], hi[4*q+1], hi[4*q+2], hi[4*q+3]);
        }
    }
    __syncthreads();

    // lane-derived ldmatrix coordinates
    const int lj = lid >> 3, lr = lid & 7;
    const int a_rl  = ((lj & 1) << 3) + lr;
    const int a_c4h = lj >> 1;
    const int b_nl  = ((lj >> 1) << 3) + lr;
    const int b_c4h = lj & 1;
    const int c2l   = 2 * (lid & 3);

    uint32_t ahr[2][4][4];   // register A fragments for layer 2 (fp16)

    // ================= layer 1 (A from smem, n-halves) =================
#pragma unroll
    for (int h = 0; h < 2; h++) {
        float acc[2][4][4];
#pragma unroll
        for (int mt = 0; mt < 2; mt++)
#pragma unroll
            for (int j = 0; j < 4; j++)
#pragma unroll
                for (int v = 0; v < 4; v++) acc[mt][j][v] = 0.f;

#pragma unroll
        for (int ks = 0; ks < 4; ks++) {
            uint32_t ahs[2][4];
#pragma unroll
            for (int mt = 0; mt < 2; mt++) {
                uint32_t off = sw_off(wbase + mt * 16 + a_rl, ks * 2 + a_c4h);
                ldsm4(ahs[mt], sb + AH + off);
            }
#pragma unroll
            for (int pp = 0; pp < 2; pp++) {
                int p = 2 * h + pp;
                uint32_t wh[4];
                uint32_t off = sw_off(p * 16 + b_nl, ks * 2 + b_c4h);
                ldsm4(wh, sb + SM_W1 + off);
#pragma unroll
                for (int mt = 0; mt < 2; mt++) {
                    mma16816(acc[mt][2*pp],   ahs[mt], wh[0], wh[1]);
                    mma16816(acc[mt][2*pp+1], ahs[mt], wh[2], wh[3]);
                }
            }
        }
        // epilogue: bias+relu -> ahr (cols 32h..32h+31)
        const float* bias = (const float*)(smem + SM_B1);
#pragma unroll
        for (int mt = 0; mt < 2; mt++)
#pragma unroll
            for (int jj = 0; jj < 4; jj++) {
                int jg = 4 * h + jj;
                int cb = 8 * jg + c2l;
                float v0 = fmaxf(acc[mt][jj][0] + bias[cb],     0.f);
                float v1 = fmaxf(acc[mt][jj][1] + bias[cb + 1], 0.f);
                float v2 = fmaxf(acc[mt][jj][2] + bias[cb],     0.f);
                float v3 = fmaxf(acc[mt][jj][3] + bias[cb + 1], 0.f);
                int s = jg >> 1, hf = jg & 1;
                ahr[mt][s][2*hf]   = pack2h(v0, v1);
                ahr[mt][s][2*hf+1] = pack2h(v2, v3);
            }
    }

    // ================= layer 2 (A from registers, n-halves, out -> smem A) ===
    __syncwarp();   // this warp's layer-1 A reads done; safe to overwrite own rows
#pragma unroll
    for (int h = 0; h < 2; h++) {
        float acc[2][4][4];
#pragma unroll
        for (int mt = 0; mt < 2; mt++)
#pragma unroll
            for (int j = 0; j < 4; j++)
#pragma unroll
                for (int v = 0; v < 4; v++) acc[mt][j][v] = 0.f;

#pragma unroll
        for (int ks = 0; ks < 4; ks++) {
#pragma unroll
            for (int pp = 0; pp < 2; pp++) {
                int p = 2 * h + pp;
                uint32_t wh[4];
                uint32_t off = sw_off(p * 16 + b_nl, ks * 2 + b_c4h);
                ldsm4(wh, sb + SM_W2 + off);
#pragma unroll
                for (int mt = 0; mt < 2; mt++) {
                    mma16816(acc[mt][2*pp],   ahr[mt][ks], wh[0], wh[1]);
                    mma16816(acc[mt][2*pp+1], ahr[mt][ks], wh[2], wh[3]);
                }
            }
        }
        // epilogue: bias+relu -> packed fp16 back into smem A (warp-private rows)
        const float* bias = (const float*)(smem + SM_B2);
#pragma unroll
        for (int mt = 0; mt < 2; mt++)
#pragma unroll
            for (int jj = 0; jj < 4; jj++) {
                int jg = 4 * h + jj;
                int cb = 8 * jg + c2l;
                float v0 = fmaxf(acc[mt][jj][0] + bias[cb],     0.f);
                float v1 = fmaxf(acc[mt][jj][1] + bias[cb + 1], 0.f);
                float v2 = fmaxf(acc[mt][jj][2] + bias[cb],     0.f);
                float v3 = fmaxf(acc[mt][jj][3] + bias[cb + 1], 0.f);
                int r0 = wbase + mt * 16 + (lid >> 2);
                uint32_t o0 = sw_off(r0,     cb >> 3) + (cb & 7) * 2;
                uint32_t o1 = sw_off(r0 + 8, cb >> 3) + (cb & 7) * 2;
                *(uint32_t*)(smem + AH + o0) = pack2h(v0, v1);
                *(uint32_t*)(smem + AH + o1) = pack2h(v2, v3);
            }
    }
    __syncwarp();

    // ================= layer 3 (A from smem, 3 n-tiles: 17 valid) =============
    float acc3[2][3][4];
#pragma unroll
    for (int mt = 0; mt < 2; mt++)
#pragma unroll
        for (int j = 0; j < 3; j++)
#pragma unroll
            for (int v = 0; v < 4; v++) acc3[mt][j][v] = 0.f;

#pragma unroll
    for (int ks = 0; ks < 4; ks++) {
        uint32_t ahs[2][4];
#pragma unroll
        for (int mt = 0; mt < 2; mt++) {
            uint32_t off = sw_off(wbase + mt * 16 + a_rl, ks * 2 + a_c4h);
            ldsm4(ahs[mt], sb + AH + off);
        }
#pragma unroll
        for (int p = 0; p < 2; p++) {
            uint32_t wh[4];
            uint32_t off = sw_off(p * 16 + b_nl, ks * 2 + b_c4h);
            ldsm4(wh, sb + SM_WO + off);
#pragma unroll
            for (int mt = 0; mt < 2; mt++) {
                mma16816(acc3[mt][2*p], ahs[mt], wh[0], wh[1]);
                if (p == 0)
                    mma16816(acc3[mt][1], ahs[mt], wh[2], wh[3]);
            }
        }
    }

    // A tile dead; alias OUT staging onto it (stride 21 -> conflict-free tail)
    __syncthreads();
    {
        const float* bos = (const float*)(smem + SM_BO);
        float* po = (float*)(smem + AH);   // 128 rows x 21 f32 = 10752B
#pragma unroll
        for (int mt = 0; mt < 2; mt++)
#pragma unroll
            for (int j = 0; j < 3; j++) {
                int cb = 8 * j + c2l;
                if (cb <= 16) {
                    int r0 = wbase + mt * 16 + (lid >> 2);
                    float bv0 = bos[cb];
                    float bv1 = (cb + 1 < 17) ? bos[cb + 1] : 0.f;
                    po[r0 * OSTRIDE + cb]           = acc3[mt][j][0] + bv0;
                    po[r0 * OSTRIDE + cb + 1]       = acc3[mt][j][1] + bv1;
                    po[(r0 + 8) * OSTRIDE + cb]     = acc3[mt][j][2] + bv0;
                    po[(r0 + 8) * OSTRIDE + cb + 1] = acc3[mt][j][3] + bv1;
                }
            }
    }
    __syncthreads();

    // ---------------- per-sample tail (all 128 threads) ----------------
    {
        const float* myo = (const float*)(smem + AH) + tid * OSTRIDE;
        const float sigma = fmaxf(myo[0], 0.f);
        const float* wrgb = (const float*)(smem + SM_WRGB);
        const float* brg  = (const float*)(smem + SM_BRGB);
        float rgbv[3];
#pragma unroll
        for (int cc = 0; cc < 3; cc++) {
            float r = brg[cc];
#pragma unroll
            for (int k = 0; k < 16; k++) r = fmaf(myo[1 + k], wrgb[k * 3 + cc], r);
            rgbv[cc] = __fdividef(1.0f, 1.0f + __expf(-r));
        }

        const float dtv   = g_dt;
        const float alpha = 1.0f - __expf(-sigma * dtv);
        const float q     = (1.0f - alpha) + 1e-10f;

        float p = q;
#pragma unroll
        for (int d = 1; d < 32; d <<= 1) {
            float u = __shfl_up_sync(0xffffffffu, p, d);
            if (lid >= d) p *= u;
        }
        __shared__ float wtot[4];
        if (lid == 31) wtot[wid] = p;
        __syncthreads();
        float pre = 1.0f;
        for (int w = 0; w < wid; w++) pre *= wtot[w];
        float excl = __shfl_up_sync(0xffffffffu, p, 1);
        if (lid == 0) excl = 1.0f;
        const float T    = pre * excl;
        const float incl = pre * p;
        const float wgt  = (T > 1e-4f) ? (T * alpha) : 0.f;

        float v0 = wgt * rgbv[0], v1 = wgt * rgbv[1], v2 = wgt * rgbv[2];
#pragma unroll
        for (int off = 16; off > 0; off >>= 1) {
            v0 += __shfl_down_sync(0xffffffffu, v0, off);
            v1 += __shfl_down_sync(0xffffffffu, v1, off);
            v2 += __shfl_down_sync(0xffffffffu, v2, off);
        }
        __shared__ float redc[4][3];
        if (lid == 0) { redc[wid][0] = v0; redc[wid][1] = v1; redc[wid][2] = v2; }
        if (tid == SS - 1) out[3 * n + ray] = incl;
        __syncthreads();
        if (tid == 0) {
            out[ray * 3 + 0] = redc[0][0] + redc[1][0] + redc[2][0] + redc[3][0];
            out[ray * 3 + 1] = redc[0][1] + redc[1][1] + redc[2][1] + redc[3][1];
            out[ray * 3 + 2] = redc[0][2] + redc[1][2] + redc[2][2] + redc[3][2];
        }
    }
}

extern "C" void kernel_launch(void* const* d_in, const int* in_sizes, int n_in,
                              void* d_out, int out_size) {
    const float* ox   = (const float*)d_in[0];
    const float* oy   = (const float*)d_in[1];
    const float* oz   = (const float*)d_in[2];
    const float* dxv  = (const float*)d_in[3];
    const float* dyv  = (const float*)d_in[4];
    const float* dzv  = (const float*)d_in[5];
    const float* tmin = (const float*)d_in[6];
    const float* tmax = (const float*)d_in[7];
    const float* W1   = (const float*)d_in[8];
    const float* b1   = (const float*)d_in[9];
    const float* W2   = (const float*)d_in[10];
    const float* b2   = (const float*)d_in[11];
    const float* Wo   = (const float*)d_in[12];
    const float* bo   = (const float*)d_in[13];
    const float* Wrgb = (const float*)d_in[14];
    const float* brgb = (const float*)d_in[15];
    float* out = (float*)d_out;
    const int n = in_sizes[0];

    cudaFuncSetAttribute(nerf_mma_kernel, cudaFuncAttributeMaxDynamicSharedMemorySize, SM_TOTAL);

    prep_kernel<<<1, 256>>>(tmin, tmax, W1, W2, Wo, n);
    nerf_mma_kernel<<<n, TPB, SM_TOTAL>>>(
        ox, oy, oz, dxv, dyv, dzv, tmin, tmax,
        b1, b2, bo, Wrgb, brgb, out, n);
}

// round 17
// speedup vs baseline: 1.1872x; 1.1872x over previous
#include <cuda_runtime.h>
#include <cuda_fp16.h>
#include <cstdint>
#include <math.h>

#define SS    128
#define LFREQ 10

__device__ float g_dt;
__device__ __align__(16) unsigned char g_wbuf[20480];   // pre-swizzled fp16 weights

#define GW_W1 0
#define GW_W2 8192
#define GW_WO 16384

// ---------------- helpers ----------------
__device__ __forceinline__ uint32_t smem_to_u32(const void* p) {
    uint32_t a;
    asm("{ .reg .u64 t; cvta.to.shared.u64 t, %1; cvt.u32.u64 %0, t; }" : "=r"(a) : "l"(p));
    return a;
}

__device__ __forceinline__ void ldsm4(uint32_t* r, uint32_t addr) {
    asm volatile("ldmatrix.sync.aligned.m8n8.x4.shared.b16 {%0,%1,%2,%3}, [%4];"
        : "=r"(r[0]), "=r"(r[1]), "=r"(r[2]), "=r"(r[3]) : "r"(addr));
}

__device__ __forceinline__ void mma16816(float* d, const uint32_t* a, uint32_t b0, uint32_t b1) {
    asm volatile("mma.sync.aligned.m16n8k16.row.col.f32.f16.f16.f32 "
        "{%0,%1,%2,%3}, {%4,%5,%6,%7}, {%8,%9}, {%0,%1,%2,%3};"
        : "+f"(d[0]), "+f"(d[1]), "+f"(d[2]), "+f"(d[3])
        : "r"(a[0]), "r"(a[1]), "r"(a[2]), "r"(a[3]), "r"(b0), "r"(b1));
}

__device__ __forceinline__ uint32_t pack2h(float a, float b) {
    __half2 hh = __floats2half2_rn(a, b);
    return *reinterpret_cast<uint32_t*>(&hh);
}

// swizzled tile byte offset: row-major, 128B rows, 16B granules XORed
__device__ __forceinline__ uint32_t sw_off(int row, int c4) {
    return (uint32_t)(row * 128 + ((c4 ^ (row & 7)) << 4));
}

// ---------------- SMEM layout (byte offsets) ----------------
#define SM_B1    0
#define SM_B2    256
#define SM_BO    512
#define SM_WRGB  640
#define SM_BRGB  832
#define SM_W     1024
#define SM_W1    (SM_W + GW_W1)
#define SM_W2    (SM_W + GW_W2)
#define SM_WO    (SM_W + GW_WO)
#define SM_A     21504   // 128 x 128B fp16 tile = 16384
#define SM_TOTAL (21504 + 16384)   // 37888

#define OSTRIDE 21       // OUT staging stride in floats (coprime with 32 banks)
#define TPB 128

// -------- prep: dt reduction + weight conversion (one CTA) --------
__global__ void prep_kernel(const float* __restrict__ tmin, const float* __restrict__ tmax,
                            const float* __restrict__ W1, const float* __restrict__ W2,
                            const float* __restrict__ Wo, int n) {
    __shared__ float red[256];
    int tid = threadIdx.x;
    float acc = 0.f;
    for (int i = tid; i < n; i += 256) acc += tmax[i] - tmin[i];
    red[tid] = acc;
    __syncthreads();
    for (int s = 128; s > 0; s >>= 1) {
        if (tid < s) red[tid] += red[tid + s];
        __syncthreads();
    }
    if (tid == 0) g_dt = (red[0] / (float)n) / (float)SS;

    for (int idx = tid; idx < 64 * 64; idx += 256) {
        int nn = idx >> 6, k = idx & 63;
        float w = (k < 63) ? W1[k * 64 + nn] : 0.f;
        __half h = __float2half_rn(w);
        uint32_t off = sw_off(nn, k >> 3) + (k & 7) * 2;
        *(uint16_t*)(g_wbuf + GW_W1 + off) = *reinterpret_cast<uint16_t*>(&h);
    }
    for (int idx = tid; idx < 64 * 64; idx += 256) {
        int nn = idx >> 6, k = idx & 63;
        float w = W2[k * 64 + nn];
        __half h = __float2half_rn(w);
        uint32_t off = sw_off(nn, k >> 3) + (k & 7) * 2;
        *(uint16_t*)(g_wbuf + GW_W2 + off) = *reinterpret_cast<uint16_t*>(&h);
    }
    for (int idx = tid; idx < 32 * 64; idx += 256) {
        int nn = idx >> 6, k = idx & 63;
        float w = (nn < 17) ? Wo[k * 17 + nn] : 0.f;
        __half h = __float2half_rn(w);
        uint32_t off = sw_off(nn, k >> 3) + (k & 7) * 2;
        *(uint16_t*)(g_wbuf + GW_WO + off) = *reinterpret_cast<uint16_t*>(&h);
    }
}

__global__ void __launch_bounds__(TPB, 5)
nerf_mma_kernel(const float* __restrict__ ox, const float* __restrict__ oy,
                const float* __restrict__ oz, const float* __restrict__ dxv,
                const float* __restrict__ dyv, const float* __restrict__ dzv,
                const float* __restrict__ tmin, const float* __restrict__ tmax,
                const float* __restrict__ b1, const float* __restrict__ b2,
                const float* __restrict__ bo,
                const float* __restrict__ Wrgb, const float* __restrict__ brgb,
                float* __restrict__ out, int n)
{
    extern __shared__ __align__(1024) char smem[];
    const uint32_t sb = smem_to_u32(smem);
    const int tid  = threadIdx.x;
    const int lid  = tid & 31;
    const int wid  = tid >> 5;            // 0..3
    const int wbase = wid * 32;           // 32 rows per warp (2 m-tiles)
    const uint32_t AH = SM_A;
    const int ray = blockIdx.x;

    // ---- stage weights (vector copy of preconverted fp16 tiles) ----
    {
        const uint4* src = (const uint4*)g_wbuf;
        uint4* dst = (uint4*)(smem + SM_W);
        for (int i = tid; i < 1280; i += TPB) dst[i] = src[i];
        float* s = (float*)smem;
        for (int i = tid; i < 64; i += TPB) s[(SM_B1 >> 2) + i] = b1[i];
        for (int i = tid; i < 64; i += TPB) s[(SM_B2 >> 2) + i] = b2[i];
        for (int i = tid; i < 17; i += TPB) s[(SM_BO >> 2) + i] = bo[i];
        for (int i = tid; i < 48; i += TPB) s[(SM_WRGB >> 2) + i] = Wrgb[i];
        for (int i = tid; i < 3;  i += TPB) s[(SM_BRGB >> 2) + i] = brgb[i];
    }

    // ---- positional encodings -> A tile (row = sample = tid, fp16) ----
    {
        const float tmn = tmin[ray], tmx = tmax[ray];
        const float t  = fmaf((float)tid * (1.0f / (float)(SS - 1)), tmx - tmn, tmn);
        float e[64];
        e[0] = fmaf(dxv[ray], t, ox[ray]);
        e[1] = fmaf(dyv[ray], t, oy[ray]);
        e[2] = fmaf(dzv[ray], t, oz[ray]);
        e[63] = 0.f;
#pragma unroll 1
        for (int c = 0; c < 3; c++) {
            float sv, cv;
            __sincosf(e[c], &sv, &cv);
#pragma unroll
            for (int f = 0; f < LFREQ; f++) {
                e[3 + 20 * c + f]      = sv;
                e[3 + 20 * c + 10 + f] = cv;
                float ns = 2.0f * sv * cv;
                float nc = fmaf(cv, cv, -(sv * sv));
                sv = ns; cv = nc;
            }
        }
#pragma unroll
        for (int q = 0; q < 8; q++) {
            uint32_t off = sw_off(tid, q);
            *(uint4*)(smem + AH + off) = make_uint4(
                pack2h(e[8*q + 0], e[8*q + 1]), pack2h(e[8*q + 2], e[8*q + 3]),
                pack2h(e[8*q + 4], e[8*q + 5]), pack2h(e[8*q + 6], e[8*q + 7]));
        }
    }
    __syncthreads();

    // lane-derived ldmatrix coordinates
    const int lj = lid >> 3, lr = lid & 7;
    const int a_rl  = ((lj & 1) << 3) + lr;
    const int a_c4h = lj >> 1;
    const int b_nl  = ((lj >> 1) << 3) + lr;
    const int b_c4h = lj & 1;
    const int c2l   = 2 * (lid & 3);

    uint32_t ahr[2][4][4];    // layer-1 output fragments (fp16)
    uint32_t ahr2[2][4][4];   // layer-2 output fragments (fp16)

    // ================= layer 1 (A from smem, n-halves) =================
#pragma unroll
    for (int h = 0; h < 2; h++) {
        float acc[2][4][4];
#pragma unroll
        for (int mt = 0; mt < 2; mt++)
#pragma unroll
            for (int j = 0; j < 4; j++)
#pragma unroll
                for (int v = 0; v < 4; v++) acc[mt][j][v] = 0.f;

#pragma unroll
        for (int ks = 0; ks < 4; ks++) {
            uint32_t ahs[2][4];
#pragma unroll
            for (int mt = 0; mt < 2; mt++) {
                uint32_t off = sw_off(wbase + mt * 16 + a_rl, ks * 2 + a_c4h);
                ldsm4(ahs[mt], sb + AH + off);
            }
#pragma unroll
            for (int pp = 0; pp < 2; pp++) {
                int p = 2 * h + pp;
                uint32_t wh[4];
                uint32_t off = sw_off(p * 16 + b_nl, ks * 2 + b_c4h);
                ldsm4(wh, sb + SM_W1 + off);
#pragma unroll
                for (int mt = 0; mt < 2; mt++) {
                    mma16816(acc[mt][2*pp],   ahs[mt], wh[0], wh[1]);
                    mma16816(acc[mt][2*pp+1], ahs[mt], wh[2], wh[3]);
                }
            }
        }
        // epilogue: bias+relu -> ahr (cols 32h..32h+31)
        const float* bias = (const float*)(smem + SM_B1);
#pragma unroll
        for (int mt = 0; mt < 2; mt++)
#pragma unroll
            for (int jj = 0; jj < 4; jj++) {
                int jg = 4 * h + jj;
                int cb = 8 * jg + c2l;
                float v0 = fmaxf(acc[mt][jj][0] + bias[cb],     0.f);
                float v1 = fmaxf(acc[mt][jj][1] + bias[cb + 1], 0.f);
                float v2 = fmaxf(acc[mt][jj][2] + bias[cb],     0.f);
                float v3 = fmaxf(acc[mt][jj][3] + bias[cb + 1], 0.f);
                int s = jg >> 1, hf = jg & 1;
                ahr[mt][s][2*hf]   = pack2h(v0, v1);
                ahr[mt][s][2*hf+1] = pack2h(v2, v3);
            }
    }

    // ================= layer 2 (A from ahr, n-halves, out -> ahr2) ===========
#pragma unroll
    for (int h = 0; h < 2; h++) {
        float acc[2][4][4];
#pragma unroll
        for (int mt = 0; mt < 2; mt++)
#pragma unroll
            for (int j = 0; j < 4; j++)
#pragma unroll
                for (int v = 0; v < 4; v++) acc[mt][j][v] = 0.f;

#pragma unroll
        for (int ks = 0; ks < 4; ks++) {
#pragma unroll
            for (int pp = 0; pp < 2; pp++) {
                int p = 2 * h + pp;
                uint32_t wh[4];
                uint32_t off = sw_off(p * 16 + b_nl, ks * 2 + b_c4h);
                ldsm4(wh, sb + SM_W2 + off);
#pragma unroll
                for (int mt = 0; mt < 2; mt++) {
                    mma16816(acc[mt][2*pp],   ahr[mt][ks], wh[0], wh[1]);
                    mma16816(acc[mt][2*pp+1], ahr[mt][ks], wh[2], wh[3]);
                }
            }
        }
        // epilogue: bias+relu -> ahr2 (cols 32h..32h+31)
        const float* bias = (const float*)(smem + SM_B2);
#pragma unroll
        for (int mt = 0; mt < 2; mt++)
#pragma unroll
            for (int jj = 0; jj < 4; jj++) {
                int jg = 4 * h + jj;
                int cb = 8 * jg + c2l;
                float v0 = fmaxf(acc[mt][jj][0] + bias[cb],     0.f);
                float v1 = fmaxf(acc[mt][jj][1] + bias[cb + 1], 0.f);
                float v2 = fmaxf(acc[mt][jj][2] + bias[cb],     0.f);
                float v3 = fmaxf(acc[mt][jj][3] + bias[cb + 1], 0.f);
                int s = jg >> 1, hf = jg & 1;
                ahr2[mt][s][2*hf]   = pack2h(v0, v1);
                ahr2[mt][s][2*hf+1] = pack2h(v2, v3);
            }
    }

    // ================= layer 3 (A from ahr2, 3 n-tiles: 17 valid) =============
    float acc3[2][3][4];
#pragma unroll
    for (int mt = 0; mt < 2; mt++)
#pragma unroll
        for (int j = 0; j < 3; j++)
#pragma unroll
            for (int v = 0; v < 4; v++) acc3[mt][j][v] = 0.f;

#pragma unroll
    for (int ks = 0; ks < 4; ks++) {
#pragma unroll
        for (int p = 0; p < 2; p++) {
            uint32_t wh[4];
            uint32_t off = sw_off(p * 16 + b_nl, ks * 2 + b_c4h);
            ldsm4(wh, sb + SM_WO + off);
#pragma unroll
            for (int mt = 0; mt < 2; mt++) {
                mma16816(acc3[mt][2*p], ahr2[mt][ks], wh[0], wh[1]);
                if (p == 0)
                    mma16816(acc3[mt][1], ahr2[mt][ks], wh[2], wh[3]);
            }
        }
    }

    // A tile dead (only layer 1 touched it); alias OUT staging onto it
    __syncthreads();
    {
        const float* bos = (const float*)(smem + SM_BO);
        float* po = (float*)(smem + AH);   // 128 rows x 21 f32 = 10752B
#pragma unroll
        for (int mt = 0; mt < 2; mt++)
#pragma unroll
            for (int j = 0; j < 3; j++) {
                int cb = 8 * j + c2l;
                if (cb <= 16) {
                    int r0 = wbase + mt * 16 + (lid >> 2);
                    float bv0 = bos[cb];
                    float bv1 = (cb + 1 < 17) ? bos[cb + 1] : 0.f;
                    po[r0 * OSTRIDE + cb]           = acc3[mt][j][0] + bv0;
                    po[r0 * OSTRIDE + cb + 1]       = acc3[mt][j][1] + bv1;
                    po[(r0 + 8) * OSTRIDE + cb]     = acc3[mt][j][2] + bv0;
                    po[(r0 + 8) * OSTRIDE + cb + 1] = acc3[mt][j][3] + bv1;
                }
            }
    }
    __syncthreads();

    // ---------------- per-sample tail (all 128 threads) ----------------
    {
        const float* myo = (const float*)(smem + AH) + tid * OSTRIDE;
        const float sigma = fmaxf(myo[0], 0.f);
        const float* wrgb = (const float*)(smem + SM_WRGB);
        const float* brg  = (const float*)(smem + SM_BRGB);
        float rgbv[3];
#pragma unroll
        for (int cc = 0; cc < 3; cc++) {
            float r = brg[cc];
#pragma unroll
            for (int k = 0; k < 16; k++) r = fmaf(myo[1 + k], wrgb[k * 3 + cc], r);
            rgbv[cc] = __fdividef(1.0f, 1.0f + __expf(-r));
        }

        const float dtv   = g_dt;
        const float alpha = 1.0f - __expf(-sigma * dtv);
        const float q     = (1.0f - alpha) + 1e-10f;

        float p = q;
#pragma unroll
        for (int d = 1; d < 32; d <<= 1) {
            float u = __shfl_up_sync(0xffffffffu, p, d);
            if (lid >= d) p *= u;
        }
        __shared__ float wtot[4];
        if (lid == 31) wtot[wid] = p;
        __syncthreads();
        float pre = 1.0f;
        for (int w = 0; w < wid; w++) pre *= wtot[w];
        float excl = __shfl_up_sync(0xffffffffu, p, 1);
        if (lid == 0) excl = 1.0f;
        const float T    = pre * excl;
        const float incl = pre * p;
        const float wgt  = (T > 1e-4f) ? (T * alpha) : 0.f;

        float v0 = wgt * rgbv[0], v1 = wgt * rgbv[1], v2 = wgt * rgbv[2];
#pragma unroll
        for (int off = 16; off > 0; off >>= 1) {
            v0 += __shfl_down_sync(0xffffffffu, v0, off);
            v1 += __shfl_down_sync(0xffffffffu, v1, off);
            v2 += __shfl_down_sync(0xffffffffu, v2, off);
        }
        __shared__ float redc[4][3];
        if (lid == 0) { redc[wid][0] = v0; redc[wid][1] = v1; redc[wid][2] = v2; }
        if (tid == SS - 1) out[3 * n + ray] = incl;
        __syncthreads();
        if (tid == 0) {
            out[ray * 3 + 0] = redc[0][0] + redc[1][0] + redc[2][0] + redc[3][0];
            out[ray * 3 + 1] = redc[0][1] + redc[1][1] + redc[2][1] + redc[3][1];
            out[ray * 3 + 2] = redc[0][2] + redc[1][2] + redc[2][2] + redc[3][2];
        }
    }
}

extern "C" void kernel_launch(void* const* d_in, const int* in_sizes, int n_in,
                              void* d_out, int out_size) {
    const float* ox   = (const float*)d_in[0];
    const float* oy   = (const float*)d_in[1];
    const float* oz   = (const float*)d_in[2];
    const float* dxv  = (const float*)d_in[3];
    const float* dyv  = (const float*)d_in[4];
    const float* dzv  = (const float*)d_in[5];
    const float* tmin = (const float*)d_in[6];
    const float* tmax = (const float*)d_in[7];
    const float* W1   = (const float*)d_in[8];
    const float* b1   = (const float*)d_in[9];
    const float* W2   = (const float*)d_in[10];
    const float* b2   = (const float*)d_in[11];
    const float* Wo   = (const float*)d_in[12];
    const float* bo   = (const float*)d_in[13];
    const float* Wrgb = (const float*)d_in[14];
    const float* brgb = (const float*)d_in[15];
    float* out = (float*)d_out;
    const int n = in_sizes[0];

    cudaFuncSetAttribute(nerf_mma_kernel, cudaFuncAttributeMaxDynamicSharedMemorySize, SM_TOTAL);

    prep_kernel<<<1, 256>>>(tmin, tmax, W1, W2, Wo, n);
    nerf_mma_kernel<<<n, TPB, SM_TOTAL>>>(
        ox, oy, oz, dxv, dyv, dzv, tmin, tmax,
        b1, b2, bo, Wrgb, brgb, out, n);
}